// round 2
// baseline (speedup 1.0000x reference)
#include <cuda_runtime.h>
#include <math.h>

#define GD 160
#define GH 160
#define GW 160
#define NP 25000
#define RADF 3.0f
#define PATCHN 20

// k = -0.5 * log2(e): fold exp(-0.5*e) into exp2(k*e)
#define KLOG2 (-0.72134752044448170368f)
// weight cutoff: w >= exp(-12)  <=>  e2 >= -12*log2(e)
#define E2T (-17.312340490667560889f)

__device__ __forceinline__ float ex2f(float x) {
    float y;
    asm("ex2.approx.f32 %0, %1;" : "=f"(y) : "f"(x));
    return y;
}

__global__ __launch_bounds__(256) void splat_kernel(
    const float* __restrict__ centers,     // [N,3]
    const float* __restrict__ log_scales,  // [N,3]
    const float* __restrict__ quats,       // [N,4]
    const float* __restrict__ rho,         // [N,2]
    float* __restrict__ out)               // [GD*GH*GW*2]
{
    __shared__ float sp[12];
    __shared__ int   si[8];

    const int n = blockIdx.x;

    if (threadIdx.x == 0) {
        const float cz = centers[n * 3 + 0] * (float)(GD - 1);
        const float cy = centers[n * 3 + 1] * (float)(GH - 1);
        const float cx = centers[n * 3 + 2] * (float)(GW - 1);

        const float s0 = expf(log_scales[n * 3 + 0]);
        const float s1 = expf(log_scales[n * 3 + 1]);
        const float s2 = expf(log_scales[n * 3 + 2]);

        const float r0v = rho[n * 2 + 0];
        const float r1v = rho[n * 2 + 1];

        const float smax = fmaxf(s0, fmaxf(s1, s2));
        const float rad  = smax * RADF;
        const float amp  = sqrtf(r0v * r0v + r1v * r1v);

        int valid = (amp >= 1e-6f && rad >= 1e-3f);

        // bounds (replicating reference mask exactly)
        const int bz = (int)floorf(cz - rad), by = (int)floorf(cy - rad), bx = (int)floorf(cx - rad);
        const int hz = (int)ceilf(cz + rad),  hy = (int)ceilf(cy + rad),  hx = (int)ceilf(cx + rad);
        const int lz = max(bz, 0), ly = max(by, 0), lx = max(bx, 0);
        const int uz = min(min(hz, GD - 1), bz + PATCHN - 1);
        const int uy = min(min(hy, GH - 1), by + PATCHN - 1);
        const int ux = min(min(hx, GW - 1), bx + PATCHN - 1);
        if (lz > uz || ly > uy || lx > ux) valid = 0;

        if (valid) {
            // quaternion -> rotation
            float qw = quats[n * 4 + 0], qx = quats[n * 4 + 1];
            float qy = quats[n * 4 + 2], qz = quats[n * 4 + 3];
            float nq = fmaxf(sqrtf(qw * qw + qx * qx + qy * qy + qz * qz), 1e-6f);
            float inq = 1.0f / nq;
            qw *= inq; qx *= inq; qy *= inq; qz *= inq;

            const float ww = qw * qw, xx = qx * qx, yy = qy * qy, zz = qz * qz;
            const float wx = qw * qx, wy = qw * qy, wz = qw * qz;
            const float xy = qx * qy, xz = qx * qz, yz = qy * qz;

            const float R00 = ww + xx - yy - zz, R01 = 2.f * (xy - wz), R02 = 2.f * (xz + wy);
            const float R10 = 2.f * (xy + wz),   R11 = ww - xx + yy - zz, R12 = 2.f * (yz - wx);
            const float R20 = 2.f * (xz - wy),   R21 = 2.f * (yz + wx),   R22 = ww - xx - yy + zz;

            const float c0 = fmaxf(s0, 1e-4f), c1 = fmaxf(s1, 1e-4f), c2 = fmaxf(s2, 1e-4f);
            const float i0 = 1.0f / (c0 * c0), i1 = 1.0f / (c1 * c1), i2 = 1.0f / (c2 * c2);

            const float p00 = R00 * R00 * i0 + R01 * R01 * i1 + R02 * R02 * i2;
            const float p11 = R10 * R10 * i0 + R11 * R11 * i1 + R12 * R12 * i2;
            const float p22 = R20 * R20 * i0 + R21 * R21 * i1 + R22 * R22 * i2;
            const float p01 = R00 * R10 * i0 + R01 * R11 * i1 + R02 * R12 * i2;
            const float p02 = R00 * R20 * i0 + R01 * R21 * i1 + R02 * R22 * i2;
            const float p12 = R10 * R20 * i0 + R11 * R21 * i1 + R12 * R22 * i2;

            // pre-scaled quadratic coefficients (includes -0.5*log2e)
            const float q00 = KLOG2 * p00;
            sp[0] = cz; sp[1] = cy; sp[2] = cx;
            sp[3] = q00;
            sp[4] = 2.0f * KLOG2 * p01;   // a01 (dy coeff of linear term)
            sp[5] = 2.0f * KLOG2 * p02;   // a02 (dx coeff)
            sp[6] = KLOG2 * p11;          // b11
            sp[7] = KLOG2 * p22;          // b22
            sp[8] = 2.0f * KLOG2 * p12;   // b12
            sp[9] = 0.5f / q00;           // inv2q (negative)
            sp[10] = r0v; sp[11] = r1v;

            si[0] = lz; si[1] = uz; si[2] = ly; si[3] = lx;
            const int nx = ux - lx + 1;
            si[4] = nx;
            si[5] = (uy - ly + 1) * nx;   // nyx
        }
        si[6] = valid;
    }
    __syncthreads();

    if (!si[6]) return;

    const float cz = sp[0], cy = sp[1], cx = sp[2];
    const float q00 = sp[3], a01 = sp[4], a02 = sp[5];
    const float b11 = sp[6], b22 = sp[7], b12 = sp[8];
    const float inv2q = sp[9];
    const float r0v = sp[10], r1v = sp[11];
    const int lz = si[0], uz = si[1], ly = si[2], lx = si[3];
    const int nx = si[4], nyx = si[5];

    for (int t = threadIdx.x; t < nyx; t += blockDim.x) {
        const int iy = t / nx;
        const int ix = t - iy * nx;
        const int Y = ly + iy;
        const int X = lx + ix;
        const float dy = (float)Y - cy;
        const float dx = (float)X - cx;

        // e2(dz) = q00*dz^2 + qcl*dz + qeyx   (all pre-scaled; want e2 >= E2T)
        const float qcl  = a01 * dy + a02 * dx;
        const float qeyx = b11 * dy * dy + (b22 * dx + b12 * dy) * dx;

        // roots of q00*dz^2 + qcl*dz + (qeyx - E2T) = 0 ; q00 < 0, keep region between roots
        const float disc = qcl * qcl - 4.0f * q00 * (qeyx - E2T);
        if (disc <= 0.0f) continue;   // whole column below cutoff

        const float s = sqrtf(disc);
        const float dz1 = (-qcl + s) * inv2q;
        const float dz2 = (-qcl - s) * inv2q;
        const float dzlo = fminf(dz1, dz2);
        const float dzhi = fmaxf(dz1, dz2);

        const int z0 = max(lz, (int)ceilf(cz + dzlo));
        const int z1 = min(uz, (int)floorf(cz + dzhi));

        const int linYX = Y * GW + X;
        for (int Z = z0; Z <= z1; ++Z) {
            const float dz = (float)Z - cz;
            const float e2 = fmaf(dz, fmaf(q00, dz, qcl), qeyx);
            const float w  = ex2f(e2);
            const float w0 = w * r0v;
            const float w1 = w * r1v;
            const size_t lin2 = 2ull * (size_t)(Z * (GH * GW) + linYX);
            asm volatile("red.global.add.v2.f32 [%0], {%1, %2};"
                         :: "l"(out + lin2), "f"(w0), "f"(w1)
                         : "memory");
        }
    }
}

extern "C" void kernel_launch(void* const* d_in, const int* in_sizes, int n_in,
                              void* d_out, int out_size) {
    const float* centers    = (const float*)d_in[0];
    const float* log_scales = (const float*)d_in[1];
    const float* quats      = (const float*)d_in[2];
    const float* rho        = (const float*)d_in[3];
    float* out = (float*)d_out;

    cudaMemsetAsync(out, 0, (size_t)out_size * sizeof(float), 0);
    splat_kernel<<<NP, 256>>>(centers, log_scales, quats, rho, out);
}

// round 3
// speedup vs baseline: 1.4437x; 1.4437x over previous
#include <cuda_runtime.h>
#include <math.h>

#define GD 160
#define GH 160
#define GW 160
#define NP 25000
#define RADF 3.0f
#define PATCHN 20

// fold exp(-0.5*e) into exp2(KLOG2*e)
#define KLOG2 (-0.72134752044448170368f)
// keep contributions with w >= exp(-12)  <=>  e2 >= -12*log2(e)
#define E2T (-17.312340490667560889f)

struct PParams {
    float cz, cy, cx;
    float q00, a01, a02;     // pre-scaled quadratic coeffs (include KLOG2)
    float b11, b22, b12;
    float inv2q;             // 0.5/q00
    float r0, r1;
    int lz, uz, ly, lx;
    int nx, nyx, valid, pad;
};

__device__ PParams g_params[NP];

__device__ __forceinline__ float ex2f(float x) {
    float y;
    asm("ex2.approx.f32 %0, %1;" : "=f"(y) : "f"(x));
    return y;
}

__global__ __launch_bounds__(256) void precompute_kernel(
    const float* __restrict__ centers,
    const float* __restrict__ log_scales,
    const float* __restrict__ quats,
    const float* __restrict__ rho)
{
    const int n = blockIdx.x * blockDim.x + threadIdx.x;
    if (n >= NP) return;

    PParams p;

    const float cz = centers[n * 3 + 0] * (float)(GD - 1);
    const float cy = centers[n * 3 + 1] * (float)(GH - 1);
    const float cx = centers[n * 3 + 2] * (float)(GW - 1);

    const float s0 = expf(log_scales[n * 3 + 0]);
    const float s1 = expf(log_scales[n * 3 + 1]);
    const float s2 = expf(log_scales[n * 3 + 2]);

    const float r0v = rho[n * 2 + 0];
    const float r1v = rho[n * 2 + 1];

    const float smax = fmaxf(s0, fmaxf(s1, s2));
    const float rad  = smax * RADF;
    const float amp  = sqrtf(r0v * r0v + r1v * r1v);

    int valid = (amp >= 1e-6f && rad >= 1e-3f);

    const int bz = (int)floorf(cz - rad), by = (int)floorf(cy - rad), bx = (int)floorf(cx - rad);
    const int hz = (int)ceilf(cz + rad),  hy = (int)ceilf(cy + rad),  hx = (int)ceilf(cx + rad);
    const int lz = max(bz, 0), ly = max(by, 0), lx = max(bx, 0);
    const int uz = min(min(hz, GD - 1), bz + PATCHN - 1);
    const int uy = min(min(hy, GH - 1), by + PATCHN - 1);
    const int ux = min(min(hx, GW - 1), bx + PATCHN - 1);
    if (lz > uz || ly > uy || lx > ux) valid = 0;

    p.valid = valid;
    if (valid) {
        float qw = quats[n * 4 + 0], qx = quats[n * 4 + 1];
        float qy = quats[n * 4 + 2], qz = quats[n * 4 + 3];
        float nq = fmaxf(sqrtf(qw * qw + qx * qx + qy * qy + qz * qz), 1e-6f);
        float inq = 1.0f / nq;
        qw *= inq; qx *= inq; qy *= inq; qz *= inq;

        const float ww = qw * qw, xx = qx * qx, yy = qy * qy, zz = qz * qz;
        const float wx = qw * qx, wy = qw * qy, wz = qw * qz;
        const float xy = qx * qy, xz = qx * qz, yz = qy * qz;

        const float R00 = ww + xx - yy - zz, R01 = 2.f * (xy - wz), R02 = 2.f * (xz + wy);
        const float R10 = 2.f * (xy + wz),   R11 = ww - xx + yy - zz, R12 = 2.f * (yz - wx);
        const float R20 = 2.f * (xz - wy),   R21 = 2.f * (yz + wx),   R22 = ww - xx - yy + zz;

        const float c0 = fmaxf(s0, 1e-4f), c1 = fmaxf(s1, 1e-4f), c2 = fmaxf(s2, 1e-4f);
        const float i0 = 1.0f / (c0 * c0), i1 = 1.0f / (c1 * c1), i2 = 1.0f / (c2 * c2);

        const float p00 = R00 * R00 * i0 + R01 * R01 * i1 + R02 * R02 * i2;
        const float p11 = R10 * R10 * i0 + R11 * R11 * i1 + R12 * R12 * i2;
        const float p22 = R20 * R20 * i0 + R21 * R21 * i1 + R22 * R22 * i2;
        const float p01 = R00 * R10 * i0 + R01 * R11 * i1 + R02 * R12 * i2;
        const float p02 = R00 * R20 * i0 + R01 * R21 * i1 + R02 * R22 * i2;
        const float p12 = R10 * R20 * i0 + R11 * R21 * i1 + R12 * R22 * i2;

        const float q00 = KLOG2 * p00;
        p.cz = cz; p.cy = cy; p.cx = cx;
        p.q00 = q00;
        p.a01 = 2.0f * KLOG2 * p01;
        p.a02 = 2.0f * KLOG2 * p02;
        p.b11 = KLOG2 * p11;
        p.b22 = KLOG2 * p22;
        p.b12 = 2.0f * KLOG2 * p12;
        p.inv2q = 0.5f / q00;
        p.r0 = r0v; p.r1 = r1v;
        p.lz = lz; p.uz = uz; p.ly = ly; p.lx = lx;
        p.nx = ux - lx + 1;
        p.nyx = (uy - ly + 1) * p.nx;
    }
    g_params[n] = p;
}

__global__ __launch_bounds__(256) void splat_kernel(float* __restrict__ out)
{
    const PParams p = g_params[blockIdx.x];   // broadcast loads, L2-resident
    if (!p.valid) return;

    const int nx = p.nx, nyx = p.nyx;
    const int lz = p.lz, uz = p.uz, ly = p.ly, lx = p.lx;

    for (int t = threadIdx.x; t < nyx; t += blockDim.x) {
        const unsigned mask = __activemask();

        const int iy = t / nx;
        const int ix = t - iy * nx;
        const int Y = ly + iy;
        const int X = lx + ix;
        const float dy = (float)Y - p.cy;
        const float dx = (float)X - p.cx;

        // e2(dz) = q00*dz^2 + qcl*dz + qeyx  (pre-scaled; keep e2 >= E2T)
        const float qcl  = p.a01 * dy + p.a02 * dx;
        const float qeyx = p.b11 * dy * dy + (p.b22 * dx + p.b12 * dy) * dx;

        // per-column z-range from quadratic roots (q00 < 0 => keep between roots)
        int z0 = 0x7FFFFFFF, z1 = -0x7FFFFFFF;
        const float disc = qcl * qcl - 4.0f * p.q00 * (qeyx - E2T);
        if (disc > 0.0f) {
            const float s = sqrtf(disc);
            const float dza = (-qcl + s) * p.inv2q;
            const float dzb = (-qcl - s) * p.inv2q;
            z0 = max(lz, (int)ceilf(p.cz + fminf(dza, dzb)));
            z1 = min(uz, (int)floorf(p.cz + fmaxf(dza, dzb)));
        }

        // warp-union range: uniform z-loop keeps RED addresses coalesced
        const int z0w = __reduce_min_sync(mask, z0);
        const int z1w = __reduce_max_sync(mask, z1);
        if (z0w > z1w) continue;

        const int linYX = Y * GW + X;
        for (int Z = z0w; Z <= z1w; ++Z) {
            const float dz = (float)Z - p.cz;
            const float e2 = fmaf(dz, fmaf(p.q00, dz, qcl), qeyx);
            if (e2 >= E2T) {
                const float w  = ex2f(e2);
                const float w0 = w * p.r0;
                const float w1 = w * p.r1;
                float* dst = out + 2u * (unsigned)(Z * (GH * GW) + linYX);
                asm volatile("red.global.add.v2.f32 [%0], {%1, %2};"
                             :: "l"(dst), "f"(w0), "f"(w1)
                             : "memory");
            }
        }
    }
}

extern "C" void kernel_launch(void* const* d_in, const int* in_sizes, int n_in,
                              void* d_out, int out_size) {
    const float* centers    = (const float*)d_in[0];
    const float* log_scales = (const float*)d_in[1];
    const float* quats      = (const float*)d_in[2];
    const float* rho        = (const float*)d_in[3];
    float* out = (float*)d_out;

    cudaMemsetAsync(out, 0, (size_t)out_size * sizeof(float), 0);
    precompute_kernel<<<(NP + 255) / 256, 256>>>(centers, log_scales, quats, rho);
    splat_kernel<<<NP, 256>>>(out);
}